// round 1
// baseline (speedup 1.0000x reference)
#include <cuda_runtime.h>

// transforms_blue: per-pixel BGR2GRAY + conditional channel boost, fp32 in/out.
// Layout [B=64, C=3, H=512, W=512], channel plane = 512*512 = 262144 floats.
// Pure streaming kernel: 3x float4 loads + 3x float4 stores per thread.

#define PLANE   262144          // floats per channel plane (512*512)
#define PLANE4  (PLANE / 4)     // 65536 float4 per plane
#define BATCH_STRIDE (3 * PLANE)
#define NPIX4   (64 * PLANE4)   // 4,194,304 float4 pixel-groups total

__device__ __forceinline__ float gray_of(float x0, float x1, float x2) {
    float u0 = floorf(x0 * 255.0f);
    float u1 = floorf(x1 * 255.0f);
    float u2 = floorf(x2 * 255.0f);
    // matches jnp.round (round-half-to-even)
    return rintf(0.114f * u0 + 0.587f * u1 + 0.299f * u2);
}

__global__ void __launch_bounds__(256) transforms_blue_kernel(
    const float* __restrict__ in, float* __restrict__ out)
{
    unsigned g = blockIdx.x * blockDim.x + threadIdx.x;
    if (g >= NPIX4) return;

    unsigned b   = g >> 16;          // g / PLANE4
    unsigned off = (g & 65535u) * 4; // float offset within plane
    unsigned base = b * BATCH_STRIDE + off;

    const float4 v0 = *reinterpret_cast<const float4*>(in + base);
    const float4 v1 = *reinterpret_cast<const float4*>(in + base + PLANE);
    const float4 v2 = *reinterpret_cast<const float4*>(in + base + 2 * PLANE);

    float4 o0, o1, o2;
    const float inv255 = 1.0f / 255.0f;

    {
        float gy = gray_of(v0.x, v1.x, v2.x);
        bool m = gy < 128.0f;
        o0.x = (m ? gy + 60.0f : gy) * inv255;
        o1.x = (m ? gy + 10.0f : gy) * inv255;
        o2.x = gy * inv255;
    }
    {
        float gy = gray_of(v0.y, v1.y, v2.y);
        bool m = gy < 128.0f;
        o0.y = (m ? gy + 60.0f : gy) * inv255;
        o1.y = (m ? gy + 10.0f : gy) * inv255;
        o2.y = gy * inv255;
    }
    {
        float gy = gray_of(v0.z, v1.z, v2.z);
        bool m = gy < 128.0f;
        o0.z = (m ? gy + 60.0f : gy) * inv255;
        o1.z = (m ? gy + 10.0f : gy) * inv255;
        o2.z = gy * inv255;
    }
    {
        float gy = gray_of(v0.w, v1.w, v2.w);
        bool m = gy < 128.0f;
        o0.w = (m ? gy + 60.0f : gy) * inv255;
        o1.w = (m ? gy + 10.0f : gy) * inv255;
        o2.w = gy * inv255;
    }

    *reinterpret_cast<float4*>(out + base)             = o0;
    *reinterpret_cast<float4*>(out + base + PLANE)     = o1;
    *reinterpret_cast<float4*>(out + base + 2 * PLANE) = o2;
}

extern "C" void kernel_launch(void* const* d_in, const int* in_sizes, int n_in,
                              void* d_out, int out_size) {
    const float* in = (const float*)d_in[0];
    float* out = (float*)d_out;
    const int threads = 256;
    const int blocks = (NPIX4 + threads - 1) / threads;
    transforms_blue_kernel<<<blocks, threads>>>(in, out);
}